// round 5
// baseline (speedup 1.0000x reference)
#include <cuda_runtime.h>
#include <cuda_fp16.h>

// Problem shapes (fixed by reference): L=4, B=8, C=256, H=64, W=64
#define LN 4
#define BN 8
#define CN 256
#define HW 4096                 // 64*64, contiguous innermost per (l,b,c)
#define SLABS (LN * BN * CN)    // 8192
#define NELEM (SLABS * HW)      // 33,554,432 floats

// Scratch (no device allocation allowed; __device__ globals are the sanctioned path)
__device__ float g_gap[SLABS];
__device__ float g_attn[SLABS];
__device__ alignas(16) __half g_h[NELEM];   // 67 MB fp16 copy of the input

// ---------------------------------------------------------------------------
// Kernel 1: GAP + fp16 compress.
// One block per (l,b,c) slab of 4096 contiguous floats; 256 thr, 4x float4.
// Input reads are __ldcs (dead after this pass -> evict-first, don't displace
// the fp16 scratch we are installing in L2). fp16 stores use default policy
// so the 67 MB scratch STAYS in L2 for the scale pass.
// ---------------------------------------------------------------------------
__global__ __launch_bounds__(256) void gap_kernel(const float* __restrict__ in) {
    const int slab = blockIdx.x;
    const float4* p = reinterpret_cast<const float4*>(in + (size_t)slab * HW);
    uint2* hq = reinterpret_cast<uint2*>(g_h + (size_t)slab * HW);
    const int tid = threadIdx.x;

    float s = 0.0f;
#pragma unroll
    for (int i = 0; i < 4; ++i) {
        const int idx = tid + i * 256;
        float4 v = __ldcs(p + idx);
        s += (v.x + v.y) + (v.z + v.w);
        __half2 h01 = __float22half2_rn(make_float2(v.x, v.y));
        __half2 h23 = __float22half2_rn(make_float2(v.z, v.w));
        uint2 packed;
        packed.x = *reinterpret_cast<unsigned int*>(&h01);
        packed.y = *reinterpret_cast<unsigned int*>(&h23);
        hq[idx] = packed;
    }

#pragma unroll
    for (int off = 16; off > 0; off >>= 1)
        s += __shfl_down_sync(0xffffffffu, s, off);

    __shared__ float warp_s[8];
    if ((tid & 31) == 0) warp_s[tid >> 5] = s;
    __syncthreads();
    if (tid < 8) {
        float t = warp_s[tid];
#pragma unroll
        for (int off = 4; off > 0; off >>= 1)
            t += __shfl_down_sync(0xffu, t, off);
        if (tid == 0) g_gap[slab] = t * (1.0f / (float)HW);
    }
}

// ---------------------------------------------------------------------------
// Kernel 2: scores + softmax-over-L. Grid = B, thread = output channel d.
// ---------------------------------------------------------------------------
__global__ __launch_bounds__(256) void attn_kernel(const float* __restrict__ Wlin) {
    const int b = blockIdx.x;
    const int d = threadIdx.x;

    __shared__ float g[LN][CN];
#pragma unroll
    for (int l = 0; l < LN; ++l)
        g[l][d] = g_gap[(l * BN + b) * CN + d];
    __syncthreads();

    const float4* wrow = reinterpret_cast<const float4*>(Wlin + (size_t)d * CN);
    float sc[LN] = {0.f, 0.f, 0.f, 0.f};
#pragma unroll 4
    for (int c4 = 0; c4 < CN / 4; ++c4) {
        float4 w = __ldg(&wrow[c4]);
        int c = c4 * 4;
#pragma unroll
        for (int l = 0; l < LN; ++l) {
            sc[l] += g[l][c + 0] * w.x;
            sc[l] += g[l][c + 1] * w.y;
            sc[l] += g[l][c + 2] * w.z;
            sc[l] += g[l][c + 3] * w.w;
        }
    }

    float m = sc[0];
#pragma unroll
    for (int l = 1; l < LN; ++l) m = fmaxf(m, sc[l]);
    float e[LN], sum = 0.f;
#pragma unroll
    for (int l = 0; l < LN; ++l) { e[l] = __expf(sc[l] - m); sum += e[l]; }
    float inv = 1.0f / sum;
#pragma unroll
    for (int l = 0; l < LN; ++l)
        g_attn[(l * BN + b) * CN + d] = e[l] * inv;
}

// ---------------------------------------------------------------------------
// Kernel 3: out = fp16(in) * attn.
// Reads the 67 MB fp16 scratch (mostly L2-resident) instead of the 134 MB
// f32 input. Each thread: 1 uint4 load (8 halves) -> 2 float4 stores.
// Scratch reads __ldcs (dead after read). Output stores __stcs (evict-first;
// they must be written back regardless, don't let them squat in L2).
// Grid = NELEM / (256*8) = 16384 blocks.
// ---------------------------------------------------------------------------
__global__ __launch_bounds__(256) void scale_kernel(float* __restrict__ out) {
    const size_t idx = (size_t)blockIdx.x * 256 + threadIdx.x;   // uint4 index (8 halves)
    const size_t fbase = idx * 8;                                // first float index
    const float a = __ldg(&g_attn[fbase >> 12]);                 // slab = fbase / 4096

    uint4 hv = __ldcs(reinterpret_cast<const uint4*>(g_h) + idx);
    float2 f0 = __half22float2(*reinterpret_cast<__half2*>(&hv.x));
    float2 f1 = __half22float2(*reinterpret_cast<__half2*>(&hv.y));
    float2 f2 = __half22float2(*reinterpret_cast<__half2*>(&hv.z));
    float2 f3 = __half22float2(*reinterpret_cast<__half2*>(&hv.w));

    float4 o0, o1;
    o0.x = f0.x * a; o0.y = f0.y * a; o0.z = f1.x * a; o0.w = f1.y * a;
    o1.x = f2.x * a; o1.y = f2.y * a; o1.z = f3.x * a; o1.w = f3.y * a;

    float4* outp = reinterpret_cast<float4*>(out) + idx * 2;
    __stcs(outp + 0, o0);
    __stcs(outp + 1, o1);
}

extern "C" void kernel_launch(void* const* d_in, const int* in_sizes, int n_in,
                              void* d_out, int out_size) {
    const float* in   = (const float*)d_in[0];   // [4,8,256,64,64]
    const float* Wlin = (const float*)d_in[1];   // [256,256]
    float* out = (float*)d_out;

    gap_kernel<<<SLABS, 256>>>(in);
    attn_kernel<<<BN, 256>>>(Wlin);
    scale_kernel<<<NELEM / (256 * 8), 256>>>(out);
}

// round 6
// speedup vs baseline: 1.1269x; 1.1269x over previous
#include <cuda_runtime.h>

// Shapes: L=4, B=8, C=256, H=W=64
#define LN 4
#define BN 8
#define CN 256
#define HW 4096
#define SLABS (LN*BN*CN)        // 8192
#define GRIDN 512
#define TPB 256

__device__ float g_gap[SLABS];
// Monotonic barrier state: never reset, safe across graph replays.
__device__ unsigned g_tickets;
__device__ unsigned g_release;

// Block p handles, for each batch b: 2 slabs (l = 2*(p>>8) + {0,1}, c = p&255).
// 128 threads per slab; each thread holds 8 float4 (32 floats) in registers.
__global__ __launch_bounds__(TPB, 4) void fused_kernel(const float* __restrict__ in,
                                                       const float* __restrict__ Wlin,
                                                       float* __restrict__ out) {
    const int p       = blockIdx.x;
    const int lhi     = p >> 8;          // 0..1
    const int c       = p & 255;
    const int tid     = threadIdx.x;
    const int slabsel = tid >> 7;        // 0..1
    const int lane    = tid & 127;
    const int l_mine  = 2 * lhi + slabsel;

    __shared__ float s_warp[8];
    __shared__ float s_scores[4];

    for (int b = 0; b < BN; ++b) {
        const int slab = (l_mine * BN + b) * CN + c;
        const float4* pin = reinterpret_cast<const float4*>(in) + (size_t)slab * 1024;

        // ---- Phase A: load slab chunk into registers, reduce for GAP ----
        float4 v[8];
#pragma unroll
        for (int j = 0; j < 8; ++j) v[j] = __ldcs(pin + lane + j * 128);

        float s = 0.0f;
#pragma unroll
        for (int j = 0; j < 8; ++j) s += (v[j].x + v[j].y) + (v[j].z + v[j].w);
#pragma unroll
        for (int off = 16; off; off >>= 1) s += __shfl_down_sync(0xffffffffu, s, off);
        if ((tid & 31) == 0) s_warp[tid >> 5] = s;
        __syncthreads();
        if (lane == 0) {
            const int base = slabsel * 4;
            float t = (s_warp[base] + s_warp[base + 1]) + (s_warp[base + 2] + s_warp[base + 3]);
            g_gap[slab] = t * (1.0f / (float)HW);
            __threadfence();                     // publish before barrier arrival
        }
        __syncthreads();

        // ---- Grid barrier (monotonic tickets; tid 0 arrives & spins) ----
        if (tid == 0) {
            unsigned tk = atomicAdd(&g_tickets, 1u);
            unsigned target = tk / GRIDN + 1u;
            if ((tk + 1u) % GRIDN == 0u) atomicAdd(&g_release, 1u);
            while (*(volatile unsigned*)&g_release < target) __nanosleep(64);
            __threadfence();                     // acquire side
        }
        __syncthreads();

        // ---- Scores for channel c: warps 0..3 each compute one l' ----
        const int w = tid >> 5;
        if (w < 4) {
            const int j = tid & 31;              // lane handles c' = j*8 .. j*8+7
            const float4* gp = reinterpret_cast<const float4*>(g_gap + (w * BN + b) * CN) + j * 2;
            const float4* wp = reinterpret_cast<const float4*>(Wlin + (size_t)c * CN) + j * 2;
            float4 g0 = gp[0], g1 = gp[1];
            float4 w0 = __ldg(wp), w1 = __ldg(wp + 1);
            float sc = g0.x * w0.x + g0.y * w0.y + g0.z * w0.z + g0.w * w0.w
                     + g1.x * w1.x + g1.y * w1.y + g1.z * w1.z + g1.w * w1.w;
#pragma unroll
            for (int off = 16; off; off >>= 1) sc += __shfl_down_sync(0xffffffffu, sc, off);
            if (j == 0) s_scores[w] = sc;
        }
        __syncthreads();

        // ---- Softmax over L (redundant per thread) + rescale registers ----
        float m = fmaxf(fmaxf(s_scores[0], s_scores[1]), fmaxf(s_scores[2], s_scores[3]));
        float e0 = __expf(s_scores[0] - m), e1 = __expf(s_scores[1] - m);
        float e2 = __expf(s_scores[2] - m), e3 = __expf(s_scores[3] - m);
        float a = __expf(s_scores[l_mine] - m) / ((e0 + e1) + (e2 + e3));

        float4* po = reinterpret_cast<float4*>(out) + (size_t)slab * 1024;
#pragma unroll
        for (int j = 0; j < 8; ++j) {
            float4 o = v[j];
            o.x *= a; o.y *= a; o.z *= a; o.w *= a;
            __stcs(po + lane + j * 128, o);
        }
        __syncthreads();   // protect s_warp/s_scores before next batch
    }
}

extern "C" void kernel_launch(void* const* d_in, const int* in_sizes, int n_in,
                              void* d_out, int out_size) {
    const float* in   = (const float*)d_in[0];   // [4,8,256,64,64]
    const float* Wlin = (const float*)d_in[1];   // [256,256]
    float* out = (float*)d_out;

    fused_kernel<<<GRIDN, TPB>>>(in, Wlin, out);
}

// round 7
// speedup vs baseline: 1.1984x; 1.0635x over previous
#include <cuda_runtime.h>

// Shapes: L=4, B=8, C=256, H=W=64
#define LN 4
#define BN 8
#define CN 256
#define HW 4096
#define SLABS (LN*BN*CN)        // 8192
#define GRIDN 512
#define TPB 256

__device__ float g_gap[SLABS];
// Monotonic barrier state: never reset, safe across graph replays.
__device__ unsigned g_tickets;
__device__ unsigned g_release;

__device__ __forceinline__ void cp16(float4* smem_dst, const float4* gmem_src) {
    unsigned saddr = (unsigned)__cvta_generic_to_shared(smem_dst);
    asm volatile("cp.async.cg.shared.global [%0], [%1], 16;" :: "r"(saddr), "l"(gmem_src));
}
__device__ __forceinline__ void cp_commit() {
    asm volatile("cp.async.commit_group;");
}
__device__ __forceinline__ void cp_wait_all() {
    asm volatile("cp.async.wait_group 0;" ::: "memory");
}

// Block p: lhi = p>>8 (0..1), c = p&255. Handles slabs (l = 2*lhi + {0,1}, c)
// for each batch. 128 threads per slab; 8 float4 per thread per batch.
// Next batch is prefetched into smem via cp.async while the current batch's
// barrier/softmax/store runs — keeps read & write streams concurrently in flight.
__global__ __launch_bounds__(TPB, 4) void fused_kernel(const float* __restrict__ in,
                                                       const float* __restrict__ Wlin,
                                                       float* __restrict__ out) {
    const int p       = blockIdx.x;
    const int lhi     = p >> 8;          // 0..1
    const int c       = p & 255;
    const int tid     = threadIdx.x;
    const int slabsel = tid >> 7;        // 0..1
    const int lane    = tid & 127;
    const int l_mine  = 2 * lhi + slabsel;

    __shared__ float4 buf[2048];         // 32 KB: two 16 KB slab chunks
    __shared__ float  s_warp[8];
    __shared__ float  s_scores[4];

    float4* mybuf = buf + slabsel * 1024;

    // Prefetch batch 0 (each thread copies exactly the 8 float4 it will read).
    {
        const int slab = (l_mine * BN + 0) * CN + c;
        const float4* src = reinterpret_cast<const float4*>(in) + (size_t)slab * 1024;
#pragma unroll
        for (int j = 0; j < 8; ++j) cp16(mybuf + lane + j * 128, src + lane + j * 128);
        cp_commit();
    }

    for (int b = 0; b < BN; ++b) {
        const int slab = (l_mine * BN + b) * CN + c;

        // ---- Consume prefetched batch b: smem -> regs, local sum ----
        cp_wait_all();
        __syncthreads();
        float4 v[8];
        float s = 0.0f;
#pragma unroll
        for (int j = 0; j < 8; ++j) {
            v[j] = mybuf[lane + j * 128];
            s += (v[j].x + v[j].y) + (v[j].z + v[j].w);
        }

        // ---- Immediately launch prefetch of batch b+1 (overlaps everything
        //      below: reduction, barrier spin, softmax, stores). Each thread
        //      overwrites only its own slots, already consumed above. ----
        if (b + 1 < BN) {
            const int nslab = (l_mine * BN + (b + 1)) * CN + c;
            const float4* src = reinterpret_cast<const float4*>(in) + (size_t)nslab * 1024;
#pragma unroll
            for (int j = 0; j < 8; ++j) cp16(mybuf + lane + j * 128, src + lane + j * 128);
            cp_commit();
        }

        // ---- Block reduce -> GAP publish ----
#pragma unroll
        for (int off = 16; off; off >>= 1) s += __shfl_down_sync(0xffffffffu, s, off);
        if ((tid & 31) == 0) s_warp[tid >> 5] = s;
        __syncthreads();
        if (lane == 0) {
            const int base = slabsel * 4;
            float t = (s_warp[base] + s_warp[base + 1]) + (s_warp[base + 2] + s_warp[base + 3]);
            g_gap[slab] = t * (1.0f / (float)HW);
            __threadfence();                 // publish before barrier arrival
        }
        __syncthreads();

        // ---- Grid barrier (monotonic tickets; graph-replay safe) ----
        if (tid == 0) {
            unsigned tk = atomicAdd(&g_tickets, 1u);
            unsigned target = tk / GRIDN + 1u;
            if ((tk + 1u) % GRIDN == 0u) atomicAdd(&g_release, 1u);
            while (*(volatile unsigned*)&g_release < target) __nanosleep(64);
            __threadfence();                 // acquire
        }
        __syncthreads();

        // ---- Scores for channel c: warps 0..3 each compute one l' ----
        const int w = tid >> 5;
        if (w < 4) {
            const int j = tid & 31;          // lane covers c' = j*8 .. j*8+7
            const float4* gp = reinterpret_cast<const float4*>(g_gap + (w * BN + b) * CN) + j * 2;
            const float4* wp = reinterpret_cast<const float4*>(Wlin + (size_t)c * CN) + j * 2;
            float4 g0 = gp[0], g1 = gp[1];
            float4 w0 = __ldg(wp), w1 = __ldg(wp + 1);
            float sc = g0.x * w0.x + g0.y * w0.y + g0.z * w0.z + g0.w * w0.w
                     + g1.x * w1.x + g1.y * w1.y + g1.z * w1.z + g1.w * w1.w;
#pragma unroll
            for (int off = 16; off; off >>= 1) sc += __shfl_down_sync(0xffffffffu, sc, off);
            if (j == 0) s_scores[w] = sc;
        }
        __syncthreads();

        // ---- Softmax over L (redundant per thread) + rescale + store ----
        float m = fmaxf(fmaxf(s_scores[0], s_scores[1]), fmaxf(s_scores[2], s_scores[3]));
        float e0 = __expf(s_scores[0] - m), e1 = __expf(s_scores[1] - m);
        float e2 = __expf(s_scores[2] - m), e3 = __expf(s_scores[3] - m);
        float a = __expf(s_scores[l_mine] - m) / ((e0 + e1) + (e2 + e3));

        float4* po = reinterpret_cast<float4*>(out) + (size_t)slab * 1024;
#pragma unroll
        for (int j = 0; j < 8; ++j) {
            float4 o = v[j];
            o.x *= a; o.y *= a; o.z *= a; o.w *= a;
            __stcs(po + lane + j * 128, o);
        }
        __syncthreads();   // protect s_warp/s_scores before next batch
    }
}

extern "C" void kernel_launch(void* const* d_in, const int* in_sizes, int n_in,
                              void* d_out, int out_size) {
    const float* in   = (const float*)d_in[0];   // [4,8,256,64,64]
    const float* Wlin = (const float*)d_in[1];   // [256,256]
    float* out = (float*)d_out;

    fused_kernel<<<GRIDN, TPB>>>(in, Wlin, out);
}

// round 8
// speedup vs baseline: 1.2841x; 1.0715x over previous
#include <cuda_runtime.h>

// Shapes: L=4, B=8, C=256, H=W=64
#define LN 4
#define BN 8
#define CN 256
#define HW 4096
#define SLABS (LN*BN*CN)        // 8192
#define GRIDN 512
#define TPB 256

__device__ float g_gap[SLABS];
// Monotonic barrier state: never reset, safe across graph replays.
__device__ unsigned g_tickets;
__device__ unsigned g_release;

__device__ __forceinline__ void cp16(float4* smem_dst, const float4* gmem_src) {
    unsigned saddr = (unsigned)__cvta_generic_to_shared(smem_dst);
    asm volatile("cp.async.cg.shared.global [%0], [%1], 16;" :: "r"(saddr), "l"(gmem_src));
}
__device__ __forceinline__ void cp_commit() {
    asm volatile("cp.async.commit_group;");
}
__device__ __forceinline__ void cp_wait_all() {
    asm volatile("cp.async.wait_group 0;" ::: "memory");
}

// Block p: lhi=p>>8, c=p&255. Half-block (128 thr) per slab, l = 2*lhi+slabsel.
// Each iteration handles a batch PAIR (b0=2i in regs via smem prefetch,
// b1=2i+1 read twice from global — second touch is an L2 hit).
// One grid barrier per pair: 4 barriers total instead of 8.
__global__ __launch_bounds__(TPB, 4) void fused_kernel(const float* __restrict__ in,
                                                       const float* __restrict__ Wlin,
                                                       float* __restrict__ out) {
    const int p       = blockIdx.x;
    const int lhi     = p >> 8;
    const int c       = p & 255;
    const int tid     = threadIdx.x;
    const int slabsel = tid >> 7;
    const int lane    = tid & 127;
    const int l_mine  = 2 * lhi + slabsel;

    __shared__ float4 buf[2048];          // 32 KB: two 16 KB slab chunks
    __shared__ float  s_warp0[8], s_warp1[8];
    __shared__ float  s_sc[2][4];

    float4* mybuf = buf + slabsel * 1024;

    // Prefetch batch 0 into smem (each thread fills exactly its own slots).
    {
        const int slab = (l_mine * BN + 0) * CN + c;
        const float4* src = reinterpret_cast<const float4*>(in) + (size_t)slab * 1024;
#pragma unroll
        for (int j = 0; j < 8; ++j) cp16(mybuf + lane + j * 128, src + lane + j * 128);
        cp_commit();
    }

    for (int i = 0; i < 4; ++i) {
        const int b0 = 2 * i, b1 = 2 * i + 1;
        const int slab0 = (l_mine * BN + b0) * CN + c;
        const int slab1 = (l_mine * BN + b1) * CN + c;
        const float4* p1 = reinterpret_cast<const float4*>(in) + (size_t)slab1 * 1024;

        // ---- b1 GAP sum: direct global loads (allocate L2 for the re-read) ----
        float s1 = 0.0f;
#pragma unroll
        for (int j = 0; j < 8; ++j) {
            float4 t = __ldg(p1 + lane + j * 128);
            s1 += (t.x + t.y) + (t.z + t.w);
        }

        // ---- b0: consume smem prefetch into registers ----
        cp_wait_all();
        float4 v[8];
        float s0 = 0.0f;
#pragma unroll
        for (int j = 0; j < 8; ++j) {
            v[j] = mybuf[lane + j * 128];
            s0 += (v[j].x + v[j].y) + (v[j].z + v[j].w);
        }

        // ---- Prefetch next pair's b0 (overlaps barrier/scores/stores) ----
        if (i < 3) {
            const int nslab = (l_mine * BN + (b0 + 2)) * CN + c;
            const float4* src = reinterpret_cast<const float4*>(in) + (size_t)nslab * 1024;
#pragma unroll
            for (int j = 0; j < 8; ++j) cp16(mybuf + lane + j * 128, src + lane + j * 128);
            cp_commit();
        }

        // ---- Block reduce both sums -> publish both gaps ----
#pragma unroll
        for (int off = 16; off; off >>= 1) {
            s0 += __shfl_down_sync(0xffffffffu, s0, off);
            s1 += __shfl_down_sync(0xffffffffu, s1, off);
        }
        if ((tid & 31) == 0) { s_warp0[tid >> 5] = s0; s_warp1[tid >> 5] = s1; }
        __syncthreads();
        if (lane == 0) {
            const int base = slabsel * 4;
            float t0 = (s_warp0[base] + s_warp0[base+1]) + (s_warp0[base+2] + s_warp0[base+3]);
            float t1 = (s_warp1[base] + s_warp1[base+1]) + (s_warp1[base+2] + s_warp1[base+3]);
            g_gap[slab0] = t0 * (1.0f / (float)HW);
            g_gap[slab1] = t1 * (1.0f / (float)HW);
            __threadfence();
        }
        __syncthreads();

        // ---- Grid barrier (monotonic tickets; graph-replay safe) ----
        if (tid == 0) {
            unsigned tk = atomicAdd(&g_tickets, 1u);
            unsigned target = tk / GRIDN + 1u;
            if ((tk + 1u) % GRIDN == 0u) atomicAdd(&g_release, 1u);
            while (*(volatile unsigned*)&g_release < target) __nanosleep(64);
            __threadfence();
        }
        __syncthreads();

        // ---- Scores: 8 warps = {batch half} x {l}. warp w: wb=w>>2, wl=w&3 ----
        {
            const int w  = tid >> 5;
            const int wb = w >> 2;            // 0 -> b0, 1 -> b1
            const int wl = w & 3;
            const int bb = wb ? b1 : b0;
            const int j  = tid & 31;
            const float4* gp = reinterpret_cast<const float4*>(g_gap + (wl * BN + bb) * CN) + j * 2;
            const float4* wp = reinterpret_cast<const float4*>(Wlin + (size_t)c * CN) + j * 2;
            float4 g0 = gp[0], g1 = gp[1];
            float4 w0 = __ldg(wp), w1 = __ldg(wp + 1);
            float sc = g0.x * w0.x + g0.y * w0.y + g0.z * w0.z + g0.w * w0.w
                     + g1.x * w1.x + g1.y * w1.y + g1.z * w1.z + g1.w * w1.w;
#pragma unroll
            for (int off = 16; off; off >>= 1) sc += __shfl_down_sync(0xffffffffu, sc, off);
            if (j == 0) s_sc[wb][wl] = sc;
        }
        __syncthreads();

        // ---- Softmax per batch, pick l_mine ----
        float a0, a1;
        {
            float m = fmaxf(fmaxf(s_sc[0][0], s_sc[0][1]), fmaxf(s_sc[0][2], s_sc[0][3]));
            float e0 = __expf(s_sc[0][0]-m), e1 = __expf(s_sc[0][1]-m);
            float e2 = __expf(s_sc[0][2]-m), e3 = __expf(s_sc[0][3]-m);
            a0 = __expf(s_sc[0][l_mine]-m) / ((e0+e1)+(e2+e3));
        }
        {
            float m = fmaxf(fmaxf(s_sc[1][0], s_sc[1][1]), fmaxf(s_sc[1][2], s_sc[1][3]));
            float e0 = __expf(s_sc[1][0]-m), e1 = __expf(s_sc[1][1]-m);
            float e2 = __expf(s_sc[1][2]-m), e3 = __expf(s_sc[1][3]-m);
            a1 = __expf(s_sc[1][l_mine]-m) / ((e0+e1)+(e2+e3));
        }

        // ---- Store b0 from registers ----
        float4* po0 = reinterpret_cast<float4*>(out) + (size_t)slab0 * 1024;
#pragma unroll
        for (int j = 0; j < 8; ++j) {
            float4 o = v[j];
            o.x *= a0; o.y *= a0; o.z *= a0; o.w *= a0;
            __stcs(po0 + lane + j * 128, o);
        }

        // ---- Store b1: re-read (L2 hit), scale, store ----
        float4* po1 = reinterpret_cast<float4*>(out) + (size_t)slab1 * 1024;
#pragma unroll
        for (int j = 0; j < 8; ++j) {
            float4 t = __ldcs(p1 + lane + j * 128);
            t.x *= a1; t.y *= a1; t.z *= a1; t.w *= a1;
            __stcs(po1 + lane + j * 128, t);
        }
        __syncthreads();   // protect shared scratch before next pair
    }
}

extern "C" void kernel_launch(void* const* d_in, const int* in_sizes, int n_in,
                              void* d_out, int out_size) {
    const float* in   = (const float*)d_in[0];   // [4,8,256,64,64]
    const float* Wlin = (const float*)d_in[1];   // [256,256]
    float* out = (float*)d_out;

    fused_kernel<<<GRIDN, TPB>>>(in, Wlin, out);
}